// round 1
// baseline (speedup 1.0000x reference)
#include <cuda_runtime.h>

// Per-node in-degree counts. 100000 nodes (line-graph). Static device scratch
// (no allocations allowed).
__device__ int g_cnt[100000];

// ---------------------------------------------------------------------------
// Kernel 1: zero the accumulator (d_out, reused as segment-sum buffer) and
// the count array. Grid-stride, float4 stores.
// ---------------------------------------------------------------------------
__global__ void zero_kernel(float4* __restrict__ out4, long nf4,
                            int* __restrict__ cnt, int n_nodes) {
    long i = (long)blockIdx.x * blockDim.x + threadIdx.x;
    long stride = (long)gridDim.x * blockDim.x;
    const float4 z = make_float4(0.f, 0.f, 0.f, 0.f);
    for (long j = i; j < nf4; j += stride) out4[j] = z;
    for (long j = i; j < n_nodes; j += stride) cnt[j] = 0;
}

// ---------------------------------------------------------------------------
// Kernel 2: scatter. One warp per edge. Each lane handles one float4 (4
// consecutive floats) of the D=128 feature row: coalesced 512B gather from
// the source row, one vectorized red.global.add.v4.f32 into the destination
// row. Lane 0 increments the destination count.
// ---------------------------------------------------------------------------
__global__ void scatter_kernel(const float* __restrict__ feats,
                               const int* __restrict__ src,
                               const int* __restrict__ dst,
                               float* __restrict__ acc,
                               int* __restrict__ cnt,
                               int n_edges) {
    long tid = (long)blockIdx.x * blockDim.x + threadIdx.x;
    int e = (int)(tid >> 5);
    int lane = (int)(tid & 31);
    if (e >= n_edges) return;

    int s = __ldg(src + e);   // warp-uniform -> single broadcast request
    int d = __ldg(dst + e);

    const float4 v = __ldg(reinterpret_cast<const float4*>(feats + (size_t)s * 128) + lane);
    float4* p = reinterpret_cast<float4*>(acc + (size_t)d * 128) + lane;

    asm volatile("red.global.add.v4.f32 [%0], {%1, %2, %3, %4};"
                 :: "l"(p), "f"(v.x), "f"(v.y), "f"(v.z), "f"(v.w)
                 : "memory");

    if (lane == 0) atomicAdd(cnt + d, 1);
}

// ---------------------------------------------------------------------------
// Kernel 3: finalize in place: out = 0.5*x + 0.5*sum/max(cnt,1).
// One thread per float4. node = i / 32 (32 float4 per 128-float row).
// ---------------------------------------------------------------------------
__global__ void finalize_kernel(const float4* __restrict__ x4,
                                float4* __restrict__ out4,
                                const int* __restrict__ cnt,
                                long nf4) {
    long i = (long)blockIdx.x * blockDim.x + threadIdx.x;
    if (i >= nf4) return;
    int node = (int)(i >> 5);
    float c = (float)__ldg(cnt + node);
    float inv = 0.5f / fmaxf(c, 1.0f);   // fold (1-alpha)=0.5 into the divide
    float4 s = out4[i];
    float4 x = __ldg(x4 + i);
    float4 r;
    r.x = 0.5f * x.x + inv * s.x;
    r.y = 0.5f * x.y + inv * s.y;
    r.z = 0.5f * x.z + inv * s.z;
    r.w = 0.5f * x.w + inv * s.w;
    out4[i] = r;
}

// ---------------------------------------------------------------------------
// Launch: d_in[0]=edge_feats [N*128] f32, d_in[1]=src [E] i32, d_in[2]=dst [E] i32
// d_out = [N*128] f32.
// ---------------------------------------------------------------------------
extern "C" void kernel_launch(void* const* d_in, const int* in_sizes, int n_in,
                              void* d_out, int out_size) {
    const float* feats = (const float*)d_in[0];
    const int* src = (const int*)d_in[1];
    const int* dst = (const int*)d_in[2];
    float* out = (float*)d_out;

    const int D = 128;
    const int n_nodes = in_sizes[0] / D;
    const int n_edges = in_sizes[1];
    const long nf4 = (long)n_nodes * (D / 4);

    int* cnt;
    cudaGetSymbolAddress((void**)&cnt, g_cnt);

    // 1. zero accumulator + counts
    {
        int threads = 256;
        int blocks = 2048;  // grid-stride
        zero_kernel<<<blocks, threads>>>((float4*)out, nf4, cnt, n_nodes);
    }

    // 2. scatter (one warp per edge)
    {
        int threads = 256;
        long total = (long)n_edges * 32;
        int blocks = (int)((total + threads - 1) / threads);
        scatter_kernel<<<blocks, threads>>>(feats, src, dst, out, cnt, n_edges);
    }

    // 3. finalize
    {
        int threads = 256;
        int blocks = (int)((nf4 + threads - 1) / threads);
        finalize_kernel<<<blocks, threads>>>((const float4*)feats, (float4*)out, cnt, nf4);
    }
}

// round 2
// speedup vs baseline: 2.3142x; 2.3142x over previous
#include <cuda_runtime.h>

// ---------------------------------------------------------------------------
// Static device scratch (no allocations allowed).
// N = 100000 nodes, E = 1600000 edges for this problem instance.
// ---------------------------------------------------------------------------
#define MAX_NODES 100000
#define MAX_EDGES 1600000
#define SCAN_ELEMS 512                       // elements per scan block
#define SCAN_BLOCKS ((MAX_NODES + SCAN_ELEMS - 1) / SCAN_ELEMS)  // 196

__device__ __align__(16) int g_cnt[MAX_NODES];        // in-degree histogram
__device__ __align__(16) int g_off[MAX_NODES + 4];    // exclusive CSR offsets
__device__ __align__(16) int g_cur[MAX_NODES];        // fill cursors
__device__ __align__(16) int g_srcs[MAX_EDGES];       // src ids sorted by dst
__device__ int g_bsum[SCAN_BLOCKS];                   // scan block sums

// ---------------------------------------------------------------------------
// 1. zero counters/cursors, set sentinel off[n] = E
// ---------------------------------------------------------------------------
__global__ void zero_kernel(int* __restrict__ cnt, int* __restrict__ cur,
                            int* __restrict__ off, int n_nodes, int n_edges) {
    int i = blockIdx.x * blockDim.x + threadIdx.x;
    int stride = gridDim.x * blockDim.x;
    for (int j = i; j < n_nodes; j += stride) { cnt[j] = 0; cur[j] = 0; }
    if (i == 0) off[n_nodes] = n_edges;
}

// ---------------------------------------------------------------------------
// 2. histogram of dst
// ---------------------------------------------------------------------------
__global__ void hist_kernel(const int* __restrict__ dst, int* __restrict__ cnt,
                            int n_edges) {
    int e = blockIdx.x * blockDim.x + threadIdx.x;
    if (e < n_edges) atomicAdd(cnt + __ldg(dst + e), 1);
}

// ---------------------------------------------------------------------------
// Scan helpers
// ---------------------------------------------------------------------------
__device__ __forceinline__ int warp_incl_scan(int v, int lane) {
#pragma unroll
    for (int o = 1; o < 32; o <<= 1) {
        int n = __shfl_up_sync(0xffffffffu, v, o);
        if (lane >= o) v += n;
    }
    return v;
}

// 3a. per-block exclusive scan of counts (128 threads x 4 elems = 512/block)
__global__ void scan_local_kernel(const int* __restrict__ cnt,
                                  int* __restrict__ off,
                                  int* __restrict__ bsum, int n) {
    __shared__ int wsum[4];
    int t = threadIdx.x;
    int lane = t & 31, warp = t >> 5;
    int base = blockIdx.x * SCAN_ELEMS + t * 4;

    int4 v = make_int4(0, 0, 0, 0);
    if (base < n) v = *reinterpret_cast<const int4*>(cnt + base);  // n % 4 == 0

    int tsum = v.x + v.y + v.z + v.w;
    int incl = warp_incl_scan(tsum, lane);
    if (lane == 31) wsum[warp] = incl;
    __syncthreads();
    int wpre = 0;
#pragma unroll
    for (int w = 0; w < 4; w++) if (w < warp) wpre += wsum[w];
    int texcl = incl - tsum + wpre;

    if (base < n) {
        int4 o;
        o.x = texcl;
        o.y = texcl + v.x;
        o.z = texcl + v.x + v.y;
        o.w = texcl + v.x + v.y + v.z;
        *reinterpret_cast<int4*>(off + base) = o;
    }
    if (t == 0) bsum[blockIdx.x] = wsum[0] + wsum[1] + wsum[2] + wsum[3];
}

// 3b. exclusive scan of the block sums (single block, 256 threads >= 196)
__global__ void scan_bsum_kernel(int* __restrict__ bsum, int nb) {
    __shared__ int wsum[8];
    int t = threadIdx.x;
    int lane = t & 31, warp = t >> 5;
    int v = (t < nb) ? bsum[t] : 0;
    int incl = warp_incl_scan(v, lane);
    if (lane == 31) wsum[warp] = incl;
    __syncthreads();
    int wpre = 0;
#pragma unroll
    for (int w = 0; w < 8; w++) if (w < warp) wpre += wsum[w];
    if (t < nb) bsum[t] = incl - v + wpre;   // exclusive
}

// 3c. add block prefixes
__global__ void scan_add_kernel(int* __restrict__ off,
                                const int* __restrict__ bsum, int n) {
    int base = blockIdx.x * SCAN_ELEMS + threadIdx.x * 4;
    if (base < n) {
        int add = __ldg(bsum + blockIdx.x);
        int4 o = *reinterpret_cast<int4*>(off + base);
        o.x += add; o.y += add; o.z += add; o.w += add;
        *reinterpret_cast<int4*>(off + base) = o;
    }
}

// ---------------------------------------------------------------------------
// 4. fill: place src ids into dst-sorted buckets
// ---------------------------------------------------------------------------
__global__ void fill_kernel(const int* __restrict__ src,
                            const int* __restrict__ dst,
                            const int* __restrict__ off,
                            int* __restrict__ cur,
                            int* __restrict__ srcs, int n_edges) {
    int e = blockIdx.x * blockDim.x + threadIdx.x;
    if (e >= n_edges) return;
    int d = __ldg(dst + e);
    int p = atomicAdd(cur + d, 1);
    srcs[__ldg(off + d) + p] = __ldg(src + e);
}

// ---------------------------------------------------------------------------
// 5. gather + finalize: one warp per node. Each lane owns one float4 column
//    of the D=128 row. Indices are loaded 32-at-a-time and broadcast by shfl.
//    out = 0.5*x + 0.5*sum/max(deg,1)
// ---------------------------------------------------------------------------
__global__ void gather_kernel(const float4* __restrict__ feats4,
                              const int* __restrict__ off,
                              const int* __restrict__ srcs,
                              float4* __restrict__ out4, int n_nodes) {
    int tid = blockIdx.x * blockDim.x + threadIdx.x;
    int node = tid >> 5;
    int lane = tid & 31;
    if (node >= n_nodes) return;

    int beg = __ldg(off + node);
    int end = __ldg(off + node + 1);

    float4 acc = make_float4(0.f, 0.f, 0.f, 0.f);
    for (int base = beg; base < end; base += 32) {
        int nchunk = min(32, end - base);
        int idx = (lane < nchunk) ? __ldg(srcs + base + lane) : 0;
        for (int j = 0; j < nchunk; j++) {
            int s = __shfl_sync(0xffffffffu, idx, j);
            float4 v = __ldg(feats4 + (size_t)s * 32 + lane);
            acc.x += v.x; acc.y += v.y; acc.z += v.z; acc.w += v.w;
        }
    }

    float deg = (float)(end - beg);
    float inv = 0.5f / fmaxf(deg, 1.0f);     // fold (1-alpha)=0.5 into divide
    float4 x = __ldg(feats4 + (size_t)node * 32 + lane);
    float4 r;
    r.x = 0.5f * x.x + inv * acc.x;
    r.y = 0.5f * x.y + inv * acc.y;
    r.z = 0.5f * x.z + inv * acc.z;
    r.w = 0.5f * x.w + inv * acc.w;
    out4[(size_t)node * 32 + lane] = r;
}

// ---------------------------------------------------------------------------
// Launch: d_in[0]=edge_feats [N*128] f32, d_in[1]=src [E] i32, d_in[2]=dst [E] i32
// ---------------------------------------------------------------------------
extern "C" void kernel_launch(void* const* d_in, const int* in_sizes, int n_in,
                              void* d_out, int out_size) {
    const float* feats = (const float*)d_in[0];
    const int* src = (const int*)d_in[1];
    const int* dst = (const int*)d_in[2];
    float* out = (float*)d_out;

    const int D = 128;
    const int n_nodes = in_sizes[0] / D;
    const int n_edges = in_sizes[1];

    int *cnt, *off, *cur, *srcs, *bsum;
    cudaGetSymbolAddress((void**)&cnt, g_cnt);
    cudaGetSymbolAddress((void**)&off, g_off);
    cudaGetSymbolAddress((void**)&cur, g_cur);
    cudaGetSymbolAddress((void**)&srcs, g_srcs);
    cudaGetSymbolAddress((void**)&bsum, g_bsum);

    int scan_blocks = (n_nodes + SCAN_ELEMS - 1) / SCAN_ELEMS;

    // 1. zero counters
    zero_kernel<<<160, 256>>>(cnt, cur, off, n_nodes, n_edges);
    // 2. histogram
    hist_kernel<<<(n_edges + 255) / 256, 256>>>(dst, cnt, n_edges);
    // 3. exclusive scan
    scan_local_kernel<<<scan_blocks, 128>>>(cnt, off, bsum, n_nodes);
    scan_bsum_kernel<<<1, 256>>>(bsum, scan_blocks);
    scan_add_kernel<<<scan_blocks, 128>>>(off, bsum, n_nodes);
    // 4. bucket fill (counting sort by dst)
    fill_kernel<<<(n_edges + 255) / 256, 256>>>(src, dst, off, cur, srcs, n_edges);
    // 5. pull-gather + finalize
    {
        long total = (long)n_nodes * 32;
        gather_kernel<<<(int)((total + 255) / 256), 256>>>(
            (const float4*)feats, off, srcs, (float4*)out, n_nodes);
    }
}